// round 13
// baseline (speedup 1.0000x reference)
#include <cuda_runtime.h>
#include <math.h>
#include <stdint.h>

#define TT 2048
#define DD 1024
#define NH 16
#define NKV 4
#define HD 64
#define NE 8
#define FF 2048
#define VV 32000
#define WIN 1024
#define NGLB 32
#define SMP2 132   // uint2 smem row pitch: conflict-free 64-bit fragment loads

// ---------------- scratch (device globals; allocation-free) ----------------
__device__ float g_x[TT * DD];
__device__ float g_h[TT * DD];
__device__ float g_q[TT * NH * HD];
__device__ float g_k[TT * NKV * HD];
__device__ float g_v[TT * NKV * HD];
__device__ float g_attn[TT * DD];
__device__ float g_cos[TT * 32];
__device__ float g_sin[TT * 32];
__device__ float g_ubuf[NE * TT * FF];
__device__ float g_abuf[NE * TT * FF];
__device__ float g_yslot[TT * 2 * DD];
__device__ float g_wslot[TT * 2];
__device__ int   g_idxl[NE * TT];
__device__ int   g_counts[NE];
__device__ float g_probsum[NE];
__device__ float g_aux;

// ---------------- small kernels ----------------
__global__ void embed_kernel(const int* __restrict__ tok, const float* __restrict__ emb,
                             float* __restrict__ x) {
    int idx = blockIdx.x * 256 + threadIdx.x;
    int t = idx >> 10, d = idx & 1023;
    x[idx] = emb[(size_t)tok[t] * DD + d];
}

__global__ void rope_table_kernel() {
    int idx = blockIdx.x * 256 + threadIdx.x;
    int t = idx >> 5, i = idx & 31;
    float inv = 1.0f / powf(500000.0f, (float)(2 * i) * (1.0f / 64.0f));
    float ang = (float)t * inv;
    g_cos[idx] = cosf(ang);
    g_sin[idx] = sinf(ang);
}

__global__ void rmsnorm_kernel(const float* __restrict__ x, const float* __restrict__ w,
                               float* __restrict__ o) {
    int t = blockIdx.x, tid = threadIdx.x;
    const float* xr = x + (size_t)t * DD;
    float ss = 0.f;
    for (int d = tid; d < DD; d += 256) { float v = xr[d]; ss += v * v; }
    #pragma unroll
    for (int off = 16; off; off >>= 1) ss += __shfl_down_sync(0xffffffffu, ss, off);
    __shared__ float sred[8];
    __shared__ float sinv;
    if ((tid & 31) == 0) sred[tid >> 5] = ss;
    __syncthreads();
    if (tid == 0) {
        float tot = 0.f;
        #pragma unroll
        for (int i = 0; i < 8; i++) tot += sred[i];
        sinv = rsqrtf(tot * (1.0f / DD) + 1.1920929e-07f);
    }
    __syncthreads();
    float inv = sinv;
    for (int d = tid; d < DD; d += 256) o[(size_t)t * DD + d] = xr[d] * inv * w[d];
}

// ---------------- flash attention (verified R10) ----------------
__global__ void __launch_bounds__(128) attn_flash_kernel(const float* __restrict__ q,
                                                         const float* __restrict__ k,
                                                         const float* __restrict__ v,
                                                         float* __restrict__ out) {
    int h = blockIdx.y;
    int qs = blockIdx.x * 128;
    int i = qs + threadIdx.x;
    int kvh = h >> 2;
    __shared__ float Ksh[32][64];
    __shared__ float Vsh[32][64];
    float qr[64];
    {
        const float* qrow = q + (size_t)i * (NH * HD) + h * HD;
        const float* ci = g_cos + i * 32;
        const float* si = g_sin + i * 32;
        #pragma unroll
        for (int d = 0; d < 32; d++) {
            float c = ci[d], s = si[d];
            float a = qrow[d], b = qrow[d + 32];
            qr[d]      = (a * c - b * s) * 0.125f;
            qr[d + 32] = (b * c + a * s) * 0.125f;
        }
    }
    float m = -1e30f, l = 0.f;
    float acc[64];
    #pragma unroll
    for (int d = 0; d < 64; d++) acc[d] = 0.f;

    for (int j0 = 0; j0 <= qs + 127; j0 += 32) {
        if (j0 >= NGLB && j0 + 31 < qs - WIN + 1) continue;
        for (int e = threadIdx.x; e < 32 * 64; e += 128) {
            int jj = e >> 6, d = e & 63;
            int j = j0 + jj;
            const float* kr = k + (size_t)j * (NKV * HD) + kvh * HD;
            float val;
            if (d < 32) {
                float c = g_cos[j * 32 + d], s = g_sin[j * 32 + d];
                val = kr[d] * c - kr[d + 32] * s;
            } else {
                int d2 = d - 32;
                float c = g_cos[j * 32 + d2], s = g_sin[j * 32 + d2];
                val = kr[d] * c + kr[d2] * s;
            }
            Ksh[jj][d] = val;
            Vsh[jj][d] = v[(size_t)j * (NKV * HD) + kvh * HD + d];
        }
        __syncthreads();
        float s[32];
        #pragma unroll
        for (int jj = 0; jj < 32; jj++) {
            float a = 0.f;
            #pragma unroll
            for (int d = 0; d < 64; d++) a += qr[d] * Ksh[jj][d];
            int j = j0 + jj;
            bool ok = (j <= i) && ((i - j) < WIN || j < NGLB);
            s[jj] = ok ? a : -1e30f;
        }
        float mt = -1e30f;
        #pragma unroll
        for (int jj = 0; jj < 32; jj++) mt = fmaxf(mt, s[jj]);
        if (mt > -1e29f) {
            float mn = fmaxf(m, mt);
            float f = expf(m - mn);
            l *= f;
            #pragma unroll
            for (int d = 0; d < 64; d++) acc[d] *= f;
            #pragma unroll
            for (int jj = 0; jj < 32; jj++) {
                float pj = expf(s[jj] - mn);
                l += pj;
                #pragma unroll
                for (int d = 0; d < 64; d++) acc[d] += pj * Vsh[jj][d];
            }
            m = mn;
        }
        __syncthreads();
    }
    float il = 1.0f / l;
    #pragma unroll
    for (int d = 0; d < 64; d++) out[(size_t)i * (NH * HD) + h * HD + d] = acc[d] * il;
}

// ---------------- tf32 3x-split tensor-core GEMM core (v2) ----------------
// Split fp32->(hi,lo) tf32 at smem store; smem holds uint2{hi,lo}.
// Inner loop: pure lds.64 + mma. Register-staged global prefetch.
__device__ __forceinline__ uint32_t cvt_tf32(float x) {
    uint32_t r; asm("cvt.rna.tf32.f32 %0, %1;" : "=r"(r) : "f"(x)); return r;
}
__device__ __forceinline__ uint2 split_tf32(float x) {
    uint32_t hi = cvt_tf32(x);
    uint32_t lo = cvt_tf32(x - __uint_as_float(hi));
    return make_uint2(hi, lo);
}

__device__ __forceinline__ void mma8(float* c, uint32_t a0, uint32_t a1, uint32_t a2,
                                     uint32_t a3, uint32_t b0, uint32_t b1) {
    asm volatile(
        "mma.sync.aligned.m16n8k8.row.col.f32.tf32.tf32.f32 "
        "{%0,%1,%2,%3}, {%4,%5,%6,%7}, {%8,%9}, {%0,%1,%2,%3};"
        : "+f"(c[0]), "+f"(c[1]), "+f"(c[2]), "+f"(c[3])
        : "r"(a0), "r"(a1), "r"(a2), "r"(a3), "r"(b0), "r"(b1));
}

// k-major scatter: element (kc+i, col)
__device__ __forceinline__ void store_split_kmajor(uint2* S, int kc, int col, float4 v) {
    S[(kc + 0) * SMP2 + col] = split_tf32(v.x);
    S[(kc + 1) * SMP2 + col] = split_tf32(v.y);
    S[(kc + 2) * SMP2 + col] = split_tf32(v.z);
    S[(kc + 3) * SMP2 + col] = split_tf32(v.w);
}
// row-major (one k row, 4 consecutive cols): two 16B stores
__device__ __forceinline__ void store_split_row(uint2* S, int krow, int col, float4 v) {
    uint2 s0 = split_tf32(v.x), s1 = split_tf32(v.y);
    uint2 s2 = split_tf32(v.z), s3 = split_tf32(v.w);
    uint4* p = (uint4*)&S[krow * SMP2 + col];
    p[0] = make_uint4(s0.x, s0.y, s1.x, s1.y);
    p[1] = make_uint4(s2.x, s2.y, s3.x, s3.y);
}

__device__ __forceinline__ void tf32_block_mma2(float (*cacc)[4][4],
                                                const uint2* As, const uint2* Bs,
                                                int lane, int wm, int wn) {
    int lr = lane >> 2, lc = lane & 3;
    #pragma unroll
    for (int ks = 0; ks < 16; ks += 8) {
        uint2 b0[4], b1[4];
        #pragma unroll
        for (int nt = 0; nt < 4; nt++) {
            b0[nt] = Bs[(ks + lc) * SMP2 + wn + nt * 8 + lr];
            b1[nt] = Bs[(ks + lc + 4) * SMP2 + wn + nt * 8 + lr];
        }
        #pragma unroll
        for (int mt = 0; mt < 4; mt++) {
            uint2 a0 = As[(ks + lc) * SMP2 + wm + mt * 16 + lr];
            uint2 a1 = As[(ks + lc) * SMP2 + wm + mt * 16 + lr + 8];
            uint2 a2 = As[(ks + lc + 4) * SMP2 + wm + mt * 16 + lr];
            uint2 a3 = As[(ks + lc + 4) * SMP2 + wm + mt * 16 + lr + 8];
            #pragma unroll
            for (int nt = 0; nt < 4; nt++) {
                mma8(cacc[mt][nt], a0.x, a1.x, a2.x, a3.x, b0[nt].x, b1[nt].x);
                mma8(cacc[mt][nt], a0.y, a1.y, a2.y, a3.y, b0[nt].x, b1[nt].x);
                mma8(cacc[mt][nt], a0.x, a1.x, a2.x, a3.x, b0[nt].y, b1[nt].y);
            }
        }
    }
}

#define TG_PROLOG                                                              \
    __shared__ uint2 As2[16 * SMP2];                                           \
    __shared__ uint2 Bs2[16 * SMP2];                                           \
    const int tid = threadIdx.x, lane = tid & 31, warp = tid >> 5;             \
    const int wm = (warp >> 2) * 64, wn = (warp & 3) * 32;                     \
    const int t2 = tid * 2;                                                    \
    const int ma0 = t2 >> 2, kca0 = (t2 & 3) * 4;                              \
    const int ma1 = (t2 + 1) >> 2, kca1 = ((t2 + 1) & 3) * 4;                  \
    float cacc[4][4][4];                                                       \
    _Pragma("unroll") for (int i = 0; i < 4; i++)                              \
        _Pragma("unroll") for (int j = 0; j < 4; j++)                          \
            _Pragma("unroll") for (int r = 0; r < 4; r++) cacc[i][j][r] = 0.f;

// ---- generic NN (B row-major [K][N]) with optional C += ----
template <bool ADD>
__global__ void __launch_bounds__(256) tgemm_nn_kernel(const float* __restrict__ A,
                                                       const float* __restrict__ B,
                                                       float* __restrict__ C,
                                                       int M, int N, int K) {
    const int m0 = blockIdx.y * 128, n0 = blockIdx.x * 128;
    TG_PROLOG
    const int bkr0 = t2 >> 5, bnc0 = (t2 & 31) * 4;
    const int bkr1 = (t2 + 1) >> 5, bnc1 = ((t2 + 1) & 31) * 4;
    float4 av0 = *(const float4*)(A + (size_t)(m0 + ma0) * K + kca0);
    float4 av1 = *(const float4*)(A + (size_t)(m0 + ma1) * K + kca1);
    float4 bv0 = *(const float4*)(B + (size_t)bkr0 * N + n0 + bnc0);
    float4 bv1 = *(const float4*)(B + (size_t)bkr1 * N + n0 + bnc1);
    for (int k0 = 0; k0 < K; k0 += 16) {
        store_split_kmajor(As2, kca0, ma0, av0);
        store_split_kmajor(As2, kca1, ma1, av1);
        store_split_row(Bs2, bkr0, bnc0, bv0);
        store_split_row(Bs2, bkr1, bnc1, bv1);
        __syncthreads();
        int kn = (k0 + 16 < K) ? (k0 + 16) : 0;
        av0 = *(const float4*)(A + (size_t)(m0 + ma0) * K + kn + kca0);
        av1 = *(const float4*)(A + (size_t)(m0 + ma1) * K + kn + kca1);
        bv0 = *(const float4*)(B + (size_t)(kn + bkr0) * N + n0 + bnc0);
        bv1 = *(const float4*)(B + (size_t)(kn + bkr1) * N + n0 + bnc1);
        tf32_block_mma2(cacc, As2, Bs2, lane, wm, wn);
        __syncthreads();
    }
    int lr = lane >> 2, lc = lane & 3;
    #pragma unroll
    for (int mt = 0; mt < 4; mt++) {
        int r0 = m0 + wm + mt * 16 + lr;
        #pragma unroll
        for (int nt = 0; nt < 4; nt++) {
            size_t c0 = (size_t)r0 * N + n0 + wn + nt * 8 + lc * 2;
            size_t c1 = (size_t)(r0 + 8) * N + n0 + wn + nt * 8 + lc * 2;
            if (ADD) {
                C[c0] += cacc[mt][nt][0]; C[c0 + 1] += cacc[mt][nt][1];
                C[c1] += cacc[mt][nt][2]; C[c1 + 1] += cacc[mt][nt][3];
            } else {
                C[c0] = cacc[mt][nt][0]; C[c0 + 1] = cacc[mt][nt][1];
                C[c1] = cacc[mt][nt][2]; C[c1 + 1] = cacc[mt][nt][3];
            }
        }
    }
}

// ---- NT (B row-major [N][K]; lm_head) ----
__global__ void __launch_bounds__(256) tgemm_nt_kernel(const float* __restrict__ A,
                                                       const float* __restrict__ B,
                                                       float* __restrict__ C,
                                                       int M, int N, int K) {
    const int m0 = blockIdx.y * 128, n0 = blockIdx.x * 128;
    TG_PROLOG
    float4 av0 = *(const float4*)(A + (size_t)(m0 + ma0) * K + kca0);
    float4 av1 = *(const float4*)(A + (size_t)(m0 + ma1) * K + kca1);
    float4 bv0 = *(const float4*)(B + (size_t)(n0 + ma0) * K + kca0);
    float4 bv1 = *(const float4*)(B + (size_t)(n0 + ma1) * K + kca1);
    for (int k0 = 0; k0 < K; k0 += 16) {
        store_split_kmajor(As2, kca0, ma0, av0);
        store_split_kmajor(As2, kca1, ma1, av1);
        store_split_kmajor(Bs2, kca0, ma0, bv0);
        store_split_kmajor(Bs2, kca1, ma1, bv1);
        __syncthreads();
        int kn = (k0 + 16 < K) ? (k0 + 16) : 0;
        av0 = *(const float4*)(A + (size_t)(m0 + ma0) * K + kn + kca0);
        av1 = *(const float4*)(A + (size_t)(m0 + ma1) * K + kn + kca1);
        bv0 = *(const float4*)(B + (size_t)(n0 + ma0) * K + kn + kca0);
        bv1 = *(const float4*)(B + (size_t)(n0 + ma1) * K + kn + kca1);
        tf32_block_mma2(cacc, As2, Bs2, lane, wm, wn);
        __syncthreads();
    }
    int lr = lane >> 2, lc = lane & 3;
    #pragma unroll
    for (int mt = 0; mt < 4; mt++) {
        int r0 = m0 + wm + mt * 16 + lr;
        #pragma unroll
        for (int nt = 0; nt < 4; nt++) {
            size_t c0 = (size_t)r0 * N + n0 + wn + nt * 8 + lc * 2;
            size_t c1 = (size_t)(r0 + 8) * N + n0 + wn + nt * 8 + lc * 2;
            C[c0] = cacc[mt][nt][0]; C[c0 + 1] = cacc[mt][nt][1];
            C[c1] = cacc[mt][nt][2]; C[c1 + 1] = cacc[mt][nt][3];
        }
    }
}

// ---- MoE up ----
__global__ void __launch_bounds__(256) tmoe_up_kernel(const float* __restrict__ X,
                                                      const float* __restrict__ Wu) {
    int e = blockIdx.z;
    int count = g_counts[e];
    int m0 = blockIdx.y * 128;
    if (m0 >= count) return;
    const float* B = Wu + (size_t)e * DD * FF;
    const int n0 = blockIdx.x * 128;
    TG_PROLOG
    const int bkr0 = t2 >> 5, bnc0 = (t2 & 31) * 4;
    const int bkr1 = (t2 + 1) >> 5, bnc1 = ((t2 + 1) & 31) * 4;
    int gi0 = m0 + ma0, gi1 = m0 + ma1;
    const float* ar0 = X + (size_t)((gi0 < count) ? (g_idxl[e * TT + gi0] >> 1) : 0) * DD;
    const float* ar1 = X + (size_t)((gi1 < count) ? (g_idxl[e * TT + gi1] >> 1) : 0) * DD;
    float4 av0 = *(const float4*)(ar0 + kca0);
    float4 av1 = *(const float4*)(ar1 + kca1);
    float4 bv0 = *(const float4*)(B + (size_t)bkr0 * FF + n0 + bnc0);
    float4 bv1 = *(const float4*)(B + (size_t)bkr1 * FF + n0 + bnc1);
    for (int k0 = 0; k0 < DD; k0 += 16) {
        store_split_kmajor(As2, kca0, ma0, av0);
        store_split_kmajor(As2, kca1, ma1, av1);
        store_split_row(Bs2, bkr0, bnc0, bv0);
        store_split_row(Bs2, bkr1, bnc1, bv1);
        __syncthreads();
        int kn = (k0 + 16 < DD) ? (k0 + 16) : 0;
        av0 = *(const float4*)(ar0 + kn + kca0);
        av1 = *(const float4*)(ar1 + kn + kca1);
        bv0 = *(const float4*)(B + (size_t)(kn + bkr0) * FF + n0 + bnc0);
        bv1 = *(const float4*)(B + (size_t)(kn + bkr1) * FF + n0 + bnc1);
        tf32_block_mma2(cacc, As2, Bs2, lane, wm, wn);
        __syncthreads();
    }
    int lr = lane >> 2, lc = lane & 3;
    #pragma unroll
    for (int mt = 0; mt < 4; mt++) {
        int r0 = m0 + wm + mt * 16 + lr;
        #pragma unroll
        for (int nt = 0; nt < 4; nt++) {
            int cn = n0 + wn + nt * 8 + lc * 2;
            if (r0 < count) {
                size_t cb = ((size_t)e * TT + r0) * FF + cn;
                g_ubuf[cb] = cacc[mt][nt][0]; g_ubuf[cb + 1] = cacc[mt][nt][1];
            }
            if (r0 + 8 < count) {
                size_t cb = ((size_t)e * TT + r0 + 8) * FF + cn;
                g_ubuf[cb] = cacc[mt][nt][2]; g_ubuf[cb + 1] = cacc[mt][nt][3];
            }
        }
    }
}

// ---- MoE gate: epilogue silu(g)*ubuf -> g_abuf ----
__global__ void __launch_bounds__(256) tmoe_gate_kernel(const float* __restrict__ X,
                                                        const float* __restrict__ Wg) {
    int e = blockIdx.z;
    int count = g_counts[e];
    int m0 = blockIdx.y * 128;
    if (m0 >= count) return;
    const float* B = Wg + (size_t)e * DD * FF;
    const int n0 = blockIdx.x * 128;
    TG_PROLOG
    const int bkr0 = t2 >> 5, bnc0 = (t2 & 31) * 4;
    const int bkr1 = (t2 + 1) >> 5, bnc1 = ((t2 + 1) & 31) * 4;
    int gi0 = m0 + ma0, gi1 = m0 + ma1;
    const float* ar0 = X + (size_t)((gi0 < count) ? (g_idxl[e * TT + gi0] >> 1) : 0) * DD;
    const float* ar1 = X + (size_t)((gi1 < count) ? (g_idxl[e * TT + gi1] >> 1) : 0) * DD;
    float4 av0 = *(const float4*)(ar0 + kca0);
    float4 av1 = *(const float4*)(ar1 + kca1);
    float4 bv0 = *(const float4*)(B + (size_t)bkr0 * FF + n0 + bnc0);
    float4 bv1 = *(const float4*)(B + (size_t)bkr1 * FF + n0 + bnc1);
    for (int k0 = 0; k0 < DD; k0 += 16) {
        store_split_kmajor(As2, kca0, ma0, av0);
        store_split_kmajor(As2, kca1, ma1, av1);
        store_split_row(Bs2, bkr0, bnc0, bv0);
        store_split_row(Bs2, bkr1, bnc1, bv1);
        __syncthreads();
        int kn = (k0 + 16 < DD) ? (k0 + 16) : 0;
        av0 = *(const float4*)(ar0 + kn + kca0);
        av1 = *(const float4*)(ar1 + kn + kca1);
        bv0 = *(const float4*)(B + (size_t)(kn + bkr0) * FF + n0 + bnc0);
        bv1 = *(const float4*)(B + (size_t)(kn + bkr1) * FF + n0 + bnc1);
        tf32_block_mma2(cacc, As2, Bs2, lane, wm, wn);
        __syncthreads();
    }
    int lr = lane >> 2, lc = lane & 3;
    #pragma unroll
    for (int mt = 0; mt < 4; mt++) {
        int r0 = m0 + wm + mt * 16 + lr;
        #pragma unroll
        for (int nt = 0; nt < 4; nt++) {
            int cn = n0 + wn + nt * 8 + lc * 2;
            #pragma unroll
            for (int half = 0; half < 2; half++) {
                int row = r0 + half * 8;
                if (row < count) {
                    size_t cb = ((size_t)e * TT + row) * FF + cn;
                    float ga = cacc[mt][nt][half * 2];
                    float gb = cacc[mt][nt][half * 2 + 1];
                    g_abuf[cb]     = ga / (1.f + expf(-ga)) * g_ubuf[cb];
                    g_abuf[cb + 1] = gb / (1.f + expf(-gb)) * g_ubuf[cb + 1];
                }
            }
        }
    }
}

// ---- MoE down: weighted scatter to g_yslot ----
__global__ void __launch_bounds__(256) tmoe_down_kernel(const float* __restrict__ Wd) {
    int e = blockIdx.z;
    int count = g_counts[e];
    int m0 = blockIdx.y * 128;
    if (m0 >= count) return;
    const float* B = Wd + (size_t)e * FF * DD;
    const int n0 = blockIdx.x * 128;
    TG_PROLOG
    const int bkr0 = t2 >> 5, bnc0 = (t2 & 31) * 4;
    const int bkr1 = (t2 + 1) >> 5, bnc1 = ((t2 + 1) & 31) * 4;
    int gi0 = m0 + ma0, gi1 = m0 + ma1;
    const float* ar0 = g_abuf + ((size_t)e * TT + ((gi0 < count) ? gi0 : 0)) * FF;
    const float* ar1 = g_abuf + ((size_t)e * TT + ((gi1 < count) ? gi1 : 0)) * FF;
    float4 av0 = *(const float4*)(ar0 + kca0);
    float4 av1 = *(const float4*)(ar1 + kca1);
    float4 bv0 = *(const float4*)(B + (size_t)bkr0 * DD + n0 + bnc0);
    float4 bv1 = *(const float4*)(B + (size_t)bkr1 * DD + n0 + bnc1);
    for (int k0 = 0; k0 < FF; k0 += 16) {
        store_split_kmajor(As2, kca0, ma0, av0);
        store_split_kmajor(As2, kca1, ma1, av1);
        store_split_row(Bs2, bkr0, bnc0, bv0);
        store_split_row(Bs2, bkr1, bnc1, bv1);
        __syncthreads();
        int kn = (k0 + 16 < FF) ? (k0 + 16) : 0;
        av0 = *(const float4*)(ar0 + kn + kca0);
        av1 = *(const float4*)(ar1 + kn + kca1);
        bv0 = *(const float4*)(B + (size_t)(kn + bkr0) * DD + n0 + bnc0);
        bv1 = *(const float4*)(B + (size_t)(kn + bkr1) * DD + n0 + bnc1);
        tf32_block_mma2(cacc, As2, Bs2, lane, wm, wn);
        __syncthreads();
    }
    int lr = lane >> 2, lc = lane & 3;
    #pragma unroll
    for (int mt = 0; mt < 4; mt++) {
        int r0 = m0 + wm + mt * 16 + lr;
        #pragma unroll
        for (int half = 0; half < 2; half++) {
            int row = r0 + half * 8;
            if (row < count) {
                int entry = g_idxl[e * TT + row];
                float wgt = g_wslot[entry];
                #pragma unroll
                for (int nt = 0; nt < 4; nt++) {
                    int cn = n0 + wn + nt * 8 + lc * 2;
                    size_t cb = (size_t)entry * DD + cn;
                    g_yslot[cb]     = cacc[mt][nt][half * 2] * wgt;
                    g_yslot[cb + 1] = cacc[mt][nt][half * 2 + 1] * wgt;
                }
            }
        }
    }
}

// ---------------- routing (verified) ----------------
__global__ void reset_router_kernel() {
    if (threadIdx.x < NE) { g_counts[threadIdx.x] = 0; g_probsum[threadIdx.x] = 0.f; }
}
__global__ void reset_aux_kernel() { g_aux = 0.f; }

__global__ void router_kernel(const float* __restrict__ X, const float* __restrict__ RW) {
    int n = blockIdx.x, tid = threadIdx.x;
    const float* xr = X + (size_t)n * DD;
    float p[NE];
    #pragma unroll
    for (int e = 0; e < NE; e++) p[e] = 0.f;
    for (int d = tid; d < DD; d += 256) {
        float xv = xr[d];
        #pragma unroll
        for (int e = 0; e < NE; e++) p[e] += xv * RW[d * NE + e];
    }
    #pragma unroll
    for (int e = 0; e < NE; e++)
        #pragma unroll
        for (int off = 16; off; off >>= 1) p[e] += __shfl_down_sync(0xffffffffu, p[e], off);
    __shared__ float sred[8][NE];
    int warp = tid >> 5, lane = tid & 31;
    if (lane == 0)
        #pragma unroll
        for (int e = 0; e < NE; e++) sred[warp][e] = p[e];
    __syncthreads();
    if (tid == 0) {
        float lg[NE];
        #pragma unroll
        for (int e = 0; e < NE; e++) {
            float s = 0.f;
            #pragma unroll
            for (int w = 0; w < 8; w++) s += sred[w][e];
            lg[e] = s;
        }
        float mx = lg[0];
        #pragma unroll
        for (int e = 1; e < NE; e++) mx = fmaxf(mx, lg[e]);
        float pb[NE], sum = 0.f;
        #pragma unroll
        for (int e = 0; e < NE; e++) { pb[e] = expf(lg[e] - mx); sum += pb[e]; }
        float isum = 1.f / sum;
        #pragma unroll
        for (int e = 0; e < NE; e++) pb[e] *= isum;
        int e1 = 0;
        #pragma unroll
        for (int e = 1; e < NE; e++) if (pb[e] > pb[e1]) e1 = e;
        int e2 = (e1 == 0) ? 1 : 0;
        #pragma unroll
        for (int e = 0; e < NE; e++) if (e != e1 && pb[e] > pb[e2]) e2 = e;
        float s2 = pb[e1] + pb[e2];
        g_wslot[2 * n]     = pb[e1] / s2;
        g_wslot[2 * n + 1] = pb[e2] / s2;
        int p1 = atomicAdd(&g_counts[e1], 1); g_idxl[e1 * TT + p1] = (n << 1);
        int p2 = atomicAdd(&g_counts[e2], 1); g_idxl[e2 * TT + p2] = (n << 1) | 1;
        #pragma unroll
        for (int e = 0; e < NE; e++) atomicAdd(&g_probsum[e], pb[e]);
    }
}

__global__ void aux_kernel() {
    float s = 0.f;
    #pragma unroll
    for (int e = 0; e < NE; e++) s += g_probsum[e] * (float)g_counts[e];
    g_aux += (float)NE * s / ((float)TT * (float)TT);
}

__global__ void combine_kernel(float* __restrict__ x) {
    int n = blockIdx.x;
    for (int d = threadIdx.x; d < DD; d += 256)
        x[(size_t)n * DD + d] += g_yslot[(size_t)(2 * n) * DD + d] +
                                 g_yslot[(size_t)(2 * n + 1) * DD + d];
}

__global__ void write_aux_kernel(float* __restrict__ out) { out[(size_t)TT * VV] = g_aux; }

// ---------------- launch ----------------
extern "C" void kernel_launch(void* const* d_in, const int* in_sizes, int n_in,
                              void* d_out, int out_size) {
    const int*   tokens = (const int*)d_in[0];
    const float* emb    = (const float*)d_in[1];
    const float* n1w    = (const float*)d_in[2];
    const float* n2w    = (const float*)d_in[3];
    const float* wq     = (const float*)d_in[4];
    const float* wk     = (const float*)d_in[5];
    const float* wv     = (const float*)d_in[6];
    const float* wo     = (const float*)d_in[7];
    const float* rw     = (const float*)d_in[8];
    const float* wg     = (const float*)d_in[9];
    const float* wu     = (const float*)d_in[10];
    const float* wd     = (const float*)d_in[11];
    const float* now    = (const float*)d_in[12];
    float* out = (float*)d_out;

    float *px, *ph, *pq, *pk, *pv, *pa;
    cudaGetSymbolAddress((void**)&px, g_x);
    cudaGetSymbolAddress((void**)&ph, g_h);
    cudaGetSymbolAddress((void**)&pq, g_q);
    cudaGetSymbolAddress((void**)&pk, g_k);
    cudaGetSymbolAddress((void**)&pv, g_v);
    cudaGetSymbolAddress((void**)&pa, g_attn);

    embed_kernel<<<TT * DD / 256, 256>>>(tokens, emb, px);
    rope_table_kernel<<<TT * 32 / 256, 256>>>();
    reset_aux_kernel<<<1, 1>>>();

    for (int l = 0; l < 2; l++) {
        rmsnorm_kernel<<<TT, 256>>>(px, n1w + (size_t)l * DD, ph);
        tgemm_nn_kernel<false><<<dim3((NH * HD) / 128, TT / 128), 256>>>(
            ph, wq + (size_t)l * DD * NH * HD, pq, TT, NH * HD, DD);
        tgemm_nn_kernel<false><<<dim3((NKV * HD) / 128, TT / 128), 256>>>(
            ph, wk + (size_t)l * DD * NKV * HD, pk, TT, NKV * HD, DD);
        tgemm_nn_kernel<false><<<dim3((NKV * HD) / 128, TT / 128), 256>>>(
            ph, wv + (size_t)l * DD * NKV * HD, pv, TT, NKV * HD, DD);
        attn_flash_kernel<<<dim3(TT / 128, NH), 128>>>(pq, pk, pv, pa);
        tgemm_nn_kernel<true><<<dim3(DD / 128, TT / 128), 256>>>(
            pa, wo + (size_t)l * NH * HD * DD, px, TT, DD, NH * HD);

        rmsnorm_kernel<<<TT, 256>>>(px, n2w + (size_t)l * DD, ph);
        reset_router_kernel<<<1, 32>>>();
        router_kernel<<<TT, 256>>>(ph, rw + (size_t)l * DD * NE);
        aux_kernel<<<1, 1>>>();

        tmoe_up_kernel<<<dim3(FF / 128, TT / 128, NE), 256>>>(
            ph, wu + (size_t)l * NE * DD * FF);
        tmoe_gate_kernel<<<dim3(FF / 128, TT / 128, NE), 256>>>(
            ph, wg + (size_t)l * NE * DD * FF);
        tmoe_down_kernel<<<dim3(DD / 128, TT / 128, NE), 256>>>(
            wd + (size_t)l * NE * FF * DD);
        combine_kernel<<<TT, 256>>>(px);
    }

    rmsnorm_kernel<<<TT, 256>>>(px, now, ph);
    tgemm_nt_kernel<<<dim3(VV / 128, TT / 128), 256>>>(ph, emb, out, TT, VV, DD);
    if (out_size > TT * VV) write_aux_kernel<<<1, 1>>>(out);
}

// round 14
// speedup vs baseline: 2.8780x; 2.8780x over previous
#include <cuda_runtime.h>
#include <cuda_bf16.h>
#include <math.h>
#include <stdint.h>

#define TT 2048
#define DD 1024
#define NH 16
#define NKV 4
#define HD 64
#define NE 8
#define FF 2048
#define VV 32000
#define WIN 1024
#define NGLB 32
#define PP 136   // plane pitch (uint32): fragment bank = (8*lc+lr) -> conflict-free

// ---------------- scratch (device globals; allocation-free) ----------------
__device__ float g_x[TT * DD];
__device__ float g_h[TT * DD];
__device__ float g_q[TT * NH * HD];
__device__ float g_k[TT * NKV * HD];
__device__ float g_v[TT * NKV * HD];
__device__ float g_attn[TT * DD];
__device__ float g_cos[TT * 32];
__device__ float g_sin[TT * 32];
__device__ float g_ubuf[NE * TT * FF];
__device__ float g_abuf[NE * TT * FF];
__device__ float g_yslot[TT * 2 * DD];
__device__ float g_wslot[TT * 2];
__device__ int   g_idxl[NE * TT];
__device__ int   g_counts[NE];
__device__ float g_probsum[NE];
__device__ float g_aux;

// ---------------- small kernels ----------------
__global__ void embed_kernel(const int* __restrict__ tok, const float* __restrict__ emb,
                             float* __restrict__ x) {
    int idx = blockIdx.x * 256 + threadIdx.x;
    int t = idx >> 10, d = idx & 1023;
    x[idx] = emb[(size_t)tok[t] * DD + d];
}

__global__ void rope_table_kernel() {
    int idx = blockIdx.x * 256 + threadIdx.x;
    int t = idx >> 5, i = idx & 31;
    float inv = 1.0f / powf(500000.0f, (float)(2 * i) * (1.0f / 64.0f));
    float ang = (float)t * inv;
    g_cos[idx] = cosf(ang);
    g_sin[idx] = sinf(ang);
}

__global__ void rmsnorm_kernel(const float* __restrict__ x, const float* __restrict__ w,
                               float* __restrict__ o) {
    int t = blockIdx.x, tid = threadIdx.x;
    const float* xr = x + (size_t)t * DD;
    float ss = 0.f;
    for (int d = tid; d < DD; d += 256) { float v = xr[d]; ss += v * v; }
    #pragma unroll
    for (int off = 16; off; off >>= 1) ss += __shfl_down_sync(0xffffffffu, ss, off);
    __shared__ float sred[8];
    __shared__ float sinv;
    if ((tid & 31) == 0) sred[tid >> 5] = ss;
    __syncthreads();
    if (tid == 0) {
        float tot = 0.f;
        #pragma unroll
        for (int i = 0; i < 8; i++) tot += sred[i];
        sinv = rsqrtf(tot * (1.0f / DD) + 1.1920929e-07f);
    }
    __syncthreads();
    float inv = sinv;
    for (int d = tid; d < DD; d += 256) o[(size_t)t * DD + d] = xr[d] * inv * w[d];
}

// ---------------- flash attention (verified R10) ----------------
__global__ void __launch_bounds__(128) attn_flash_kernel(const float* __restrict__ q,
                                                         const float* __restrict__ k,
                                                         const float* __restrict__ v,
                                                         float* __restrict__ out) {
    int h = blockIdx.y;
    int qs = blockIdx.x * 128;
    int i = qs + threadIdx.x;
    int kvh = h >> 2;
    __shared__ float Ksh[32][64];
    __shared__ float Vsh[32][64];
    float qr[64];
    {
        const float* qrow = q + (size_t)i * (NH * HD) + h * HD;
        const float* ci = g_cos + i * 32;
        const float* si = g_sin + i * 32;
        #pragma unroll
        for (int d = 0; d < 32; d++) {
            float c = ci[d], s = si[d];
            float a = qrow[d], b = qrow[d + 32];
            qr[d]      = (a * c - b * s) * 0.125f;
            qr[d + 32] = (b * c + a * s) * 0.125f;
        }
    }
    float m = -1e30f, l = 0.f;
    float acc[64];
    #pragma unroll
    for (int d = 0; d < 64; d++) acc[d] = 0.f;

    for (int j0 = 0; j0 <= qs + 127; j0 += 32) {
        if (j0 >= NGLB && j0 + 31 < qs - WIN + 1) continue;
        for (int e = threadIdx.x; e < 32 * 64; e += 128) {
            int jj = e >> 6, d = e & 63;
            int j = j0 + jj;
            const float* kr = k + (size_t)j * (NKV * HD) + kvh * HD;
            float val;
            if (d < 32) {
                float c = g_cos[j * 32 + d], s = g_sin[j * 32 + d];
                val = kr[d] * c - kr[d + 32] * s;
            } else {
                int d2 = d - 32;
                float c = g_cos[j * 32 + d2], s = g_sin[j * 32 + d2];
                val = kr[d] * c + kr[d2] * s;
            }
            Ksh[jj][d] = val;
            Vsh[jj][d] = v[(size_t)j * (NKV * HD) + kvh * HD + d];
        }
        __syncthreads();
        float s[32];
        #pragma unroll
        for (int jj = 0; jj < 32; jj++) {
            float a = 0.f;
            #pragma unroll
            for (int d = 0; d < 64; d++) a += qr[d] * Ksh[jj][d];
            int j = j0 + jj;
            bool ok = (j <= i) && ((i - j) < WIN || j < NGLB);
            s[jj] = ok ? a : -1e30f;
        }
        float mt = -1e30f;
        #pragma unroll
        for (int jj = 0; jj < 32; jj++) mt = fmaxf(mt, s[jj]);
        if (mt > -1e29f) {
            float mn = fmaxf(m, mt);
            float f = expf(m - mn);
            l *= f;
            #pragma unroll
            for (int d = 0; d < 64; d++) acc[d] *= f;
            #pragma unroll
            for (int jj = 0; jj < 32; jj++) {
                float pj = expf(s[jj] - mn);
                l += pj;
                #pragma unroll
                for (int d = 0; d < 64; d++) acc[d] += pj * Vsh[jj][d];
            }
            m = mn;
        }
        __syncthreads();
    }
    float il = 1.0f / l;
    #pragma unroll
    for (int d = 0; d < 64; d++) out[(size_t)i * (NH * HD) + h * HD + d] = acc[d] * il;
}

// ---------------- bf16x3 tensor-core GEMM core ----------------
// fp32 -> (bf16 hi, bf16 lo) split at smem store into k-pair-packed planes.
// mma.m16n8k16: 3 terms (hi*hi + lo*hi + hi*lo). C layout identical to m16n8k8.
__device__ __forceinline__ void split2(float x0, float x1, uint32_t& hi, uint32_t& lo) {
    __nv_bfloat162 h = __floats2bfloat162_rn(x0, x1);   // .x = x0 (low half)
    float h0 = __bfloat162float(h.x), h1 = __bfloat162float(h.y);
    __nv_bfloat162 l = __floats2bfloat162_rn(x0 - h0, x1 - h1);
    hi = *reinterpret_cast<uint32_t*>(&h);
    lo = *reinterpret_cast<uint32_t*>(&l);
}

// float4 along K at column col (kc multiple of 4): pairs (kc/2, kc/2+1)
__device__ __forceinline__ void store_kpairs(uint32_t* Phi, uint32_t* Plo,
                                             int kc, int col, float4 v) {
    uint32_t h0, l0, h1, l1;
    split2(v.x, v.y, h0, l0);
    split2(v.z, v.w, h1, l1);
    int q = kc >> 1;
    Phi[q * PP + col] = h0;       Plo[q * PP + col] = l0;
    Phi[(q + 1) * PP + col] = h1; Plo[(q + 1) * PP + col] = l1;
}

// two float4 from k-rows (2q, 2q+1) at cols nc..nc+3
__device__ __forceinline__ void store_npairs(uint32_t* Phi, uint32_t* Plo,
                                             int q, int nc, float4 v0, float4 v1) {
    uint32_t h, l;
    split2(v0.x, v1.x, h, l); Phi[q * PP + nc] = h;     Plo[q * PP + nc] = l;
    split2(v0.y, v1.y, h, l); Phi[q * PP + nc + 1] = h; Plo[q * PP + nc + 1] = l;
    split2(v0.z, v1.z, h, l); Phi[q * PP + nc + 2] = h; Plo[q * PP + nc + 2] = l;
    split2(v0.w, v1.w, h, l); Phi[q * PP + nc + 3] = h; Plo[q * PP + nc + 3] = l;
}

__device__ __forceinline__ void mma16(float* c, uint32_t a0, uint32_t a1, uint32_t a2,
                                      uint32_t a3, uint32_t b0, uint32_t b1) {
    asm volatile(
        "mma.sync.aligned.m16n8k16.row.col.f32.bf16.bf16.f32 "
        "{%0,%1,%2,%3}, {%4,%5,%6,%7}, {%8,%9}, {%0,%1,%2,%3};"
        : "+f"(c[0]), "+f"(c[1]), "+f"(c[2]), "+f"(c[3])
        : "r"(a0), "r"(a1), "r"(a2), "r"(a3), "r"(b0), "r"(b1));
}

__device__ __forceinline__ void bf16_block_mma(float (*cacc)[4][4],
                                               const uint32_t* Ahi, const uint32_t* Alo,
                                               const uint32_t* Bhi, const uint32_t* Blo,
                                               int lane, int wm, int wn) {
    int lr = lane >> 2, lc = lane & 3;
    uint32_t bh0[4], bh1[4], bl0[4], bl1[4];
    #pragma unroll
    for (int nt = 0; nt < 4; nt++) {
        int n = wn + nt * 8 + lr;
        bh0[nt] = Bhi[lc * PP + n];       bh1[nt] = Bhi[(lc + 4) * PP + n];
        bl0[nt] = Blo[lc * PP + n];       bl1[nt] = Blo[(lc + 4) * PP + n];
    }
    #pragma unroll
    for (int mt = 0; mt < 4; mt++) {
        int m = wm + mt * 16 + lr;
        uint32_t ah0 = Ahi[lc * PP + m],       ah1 = Ahi[lc * PP + m + 8];
        uint32_t ah2 = Ahi[(lc + 4) * PP + m], ah3 = Ahi[(lc + 4) * PP + m + 8];
        uint32_t al0 = Alo[lc * PP + m],       al1 = Alo[lc * PP + m + 8];
        uint32_t al2 = Alo[(lc + 4) * PP + m], al3 = Alo[(lc + 4) * PP + m + 8];
        #pragma unroll
        for (int nt = 0; nt < 4; nt++) {
            mma16(cacc[mt][nt], ah0, ah1, ah2, ah3, bh0[nt], bh1[nt]);
            mma16(cacc[mt][nt], al0, al1, al2, al3, bh0[nt], bh1[nt]);
            mma16(cacc[mt][nt], ah0, ah1, ah2, ah3, bl0[nt], bl1[nt]);
        }
    }
}

#define TB_PROLOG                                                              \
    __shared__ uint32_t Ahi[8 * PP], Alo[8 * PP], Bhi[8 * PP], Blo[8 * PP];    \
    const int tid = threadIdx.x, lane = tid & 31, warp = tid >> 5;             \
    const int wm = (warp >> 2) * 64, wn = (warp & 3) * 32;                     \
    const int t2 = tid * 2;                                                    \
    const int ma0 = t2 >> 2, kca0 = (t2 & 3) * 4;                              \
    const int ma1 = (t2 + 1) >> 2, kca1 = ((t2 + 1) & 3) * 4;                  \
    const int bq = tid >> 5, bnc = (tid & 31) * 4;                             \
    float cacc[4][4][4];                                                       \
    _Pragma("unroll") for (int i = 0; i < 4; i++)                              \
        _Pragma("unroll") for (int j = 0; j < 4; j++)                          \
            _Pragma("unroll") for (int r = 0; r < 4; r++) cacc[i][j][r] = 0.f;

// ---- generic NN (B row-major [K][N]) with optional C += ----
template <bool ADD>
__global__ void __launch_bounds__(256) tgemm_nn_kernel(const float* __restrict__ A,
                                                       const float* __restrict__ B,
                                                       float* __restrict__ C,
                                                       int M, int N, int K) {
    const int m0 = blockIdx.y * 128, n0 = blockIdx.x * 128;
    TB_PROLOG
    for (int k0 = 0; k0 < K; k0 += 16) {
        float4 av0 = *(const float4*)(A + (size_t)(m0 + ma0) * K + k0 + kca0);
        float4 av1 = *(const float4*)(A + (size_t)(m0 + ma1) * K + k0 + kca1);
        float4 bv0 = *(const float4*)(B + (size_t)(k0 + 2 * bq) * N + n0 + bnc);
        float4 bv1 = *(const float4*)(B + (size_t)(k0 + 2 * bq + 1) * N + n0 + bnc);
        store_kpairs(Ahi, Alo, kca0, ma0, av0);
        store_kpairs(Ahi, Alo, kca1, ma1, av1);
        store_npairs(Bhi, Blo, bq, bnc, bv0, bv1);
        __syncthreads();
        bf16_block_mma(cacc, Ahi, Alo, Bhi, Blo, lane, wm, wn);
        __syncthreads();
    }
    int lr = lane >> 2, lc = lane & 3;
    #pragma unroll
    for (int mt = 0; mt < 4; mt++) {
        int r0 = m0 + wm + mt * 16 + lr;
        #pragma unroll
        for (int nt = 0; nt < 4; nt++) {
            size_t c0 = (size_t)r0 * N + n0 + wn + nt * 8 + lc * 2;
            size_t c1 = (size_t)(r0 + 8) * N + n0 + wn + nt * 8 + lc * 2;
            if (ADD) {
                C[c0] += cacc[mt][nt][0]; C[c0 + 1] += cacc[mt][nt][1];
                C[c1] += cacc[mt][nt][2]; C[c1 + 1] += cacc[mt][nt][3];
            } else {
                C[c0] = cacc[mt][nt][0]; C[c0 + 1] = cacc[mt][nt][1];
                C[c1] = cacc[mt][nt][2]; C[c1 + 1] = cacc[mt][nt][3];
            }
        }
    }
}

// ---- NT (B row-major [N][K]; lm_head) ----
__global__ void __launch_bounds__(256) tgemm_nt_kernel(const float* __restrict__ A,
                                                       const float* __restrict__ B,
                                                       float* __restrict__ C,
                                                       int M, int N, int K) {
    const int m0 = blockIdx.y * 128, n0 = blockIdx.x * 128;
    TB_PROLOG
    for (int k0 = 0; k0 < K; k0 += 16) {
        float4 av0 = *(const float4*)(A + (size_t)(m0 + ma0) * K + k0 + kca0);
        float4 av1 = *(const float4*)(A + (size_t)(m0 + ma1) * K + k0 + kca1);
        float4 bv0 = *(const float4*)(B + (size_t)(n0 + ma0) * K + k0 + kca0);
        float4 bv1 = *(const float4*)(B + (size_t)(n0 + ma1) * K + k0 + kca1);
        store_kpairs(Ahi, Alo, kca0, ma0, av0);
        store_kpairs(Ahi, Alo, kca1, ma1, av1);
        store_kpairs(Bhi, Blo, kca0, ma0, bv0);
        store_kpairs(Bhi, Blo, kca1, ma1, bv1);
        __syncthreads();
        bf16_block_mma(cacc, Ahi, Alo, Bhi, Blo, lane, wm, wn);
        __syncthreads();
    }
    int lr = lane >> 2, lc = lane & 3;
    #pragma unroll
    for (int mt = 0; mt < 4; mt++) {
        int r0 = m0 + wm + mt * 16 + lr;
        #pragma unroll
        for (int nt = 0; nt < 4; nt++) {
            size_t c0 = (size_t)r0 * N + n0 + wn + nt * 8 + lc * 2;
            size_t c1 = (size_t)(r0 + 8) * N + n0 + wn + nt * 8 + lc * 2;
            C[c0] = cacc[mt][nt][0]; C[c0 + 1] = cacc[mt][nt][1];
            C[c1] = cacc[mt][nt][2]; C[c1 + 1] = cacc[mt][nt][3];
        }
    }
}

// ---- MoE up ----
__global__ void __launch_bounds__(256) tmoe_up_kernel(const float* __restrict__ X,
                                                      const float* __restrict__ Wu) {
    int e = blockIdx.z;
    int count = g_counts[e];
    int m0 = blockIdx.y * 128;
    if (m0 >= count) return;
    const float* B = Wu + (size_t)e * DD * FF;
    const int n0 = blockIdx.x * 128;
    TB_PROLOG
    int gi0 = m0 + ma0, gi1 = m0 + ma1;
    const float* ar0 = X + (size_t)((gi0 < count) ? (g_idxl[e * TT + gi0] >> 1) : 0) * DD;
    const float* ar1 = X + (size_t)((gi1 < count) ? (g_idxl[e * TT + gi1] >> 1) : 0) * DD;
    for (int k0 = 0; k0 < DD; k0 += 16) {
        float4 av0 = *(const float4*)(ar0 + k0 + kca0);
        float4 av1 = *(const float4*)(ar1 + k0 + kca1);
        float4 bv0 = *(const float4*)(B + (size_t)(k0 + 2 * bq) * FF + n0 + bnc);
        float4 bv1 = *(const float4*)(B + (size_t)(k0 + 2 * bq + 1) * FF + n0 + bnc);
        store_kpairs(Ahi, Alo, kca0, ma0, av0);
        store_kpairs(Ahi, Alo, kca1, ma1, av1);
        store_npairs(Bhi, Blo, bq, bnc, bv0, bv1);
        __syncthreads();
        bf16_block_mma(cacc, Ahi, Alo, Bhi, Blo, lane, wm, wn);
        __syncthreads();
    }
    int lr = lane >> 2, lc = lane & 3;
    #pragma unroll
    for (int mt = 0; mt < 4; mt++) {
        int r0 = m0 + wm + mt * 16 + lr;
        #pragma unroll
        for (int nt = 0; nt < 4; nt++) {
            int cn = n0 + wn + nt * 8 + lc * 2;
            if (r0 < count) {
                size_t cb = ((size_t)e * TT + r0) * FF + cn;
                g_ubuf[cb] = cacc[mt][nt][0]; g_ubuf[cb + 1] = cacc[mt][nt][1];
            }
            if (r0 + 8 < count) {
                size_t cb = ((size_t)e * TT + r0 + 8) * FF + cn;
                g_ubuf[cb] = cacc[mt][nt][2]; g_ubuf[cb + 1] = cacc[mt][nt][3];
            }
        }
    }
}

// ---- MoE gate: epilogue silu(g)*ubuf -> g_abuf ----
__global__ void __launch_bounds__(256) tmoe_gate_kernel(const float* __restrict__ X,
                                                        const float* __restrict__ Wg) {
    int e = blockIdx.z;
    int count = g_counts[e];
    int m0 = blockIdx.y * 128;
    if (m0 >= count) return;
    const float* B = Wg + (size_t)e * DD * FF;
    const int n0 = blockIdx.x * 128;
    TB_PROLOG
    int gi0 = m0 + ma0, gi1 = m0 + ma1;
    const float* ar0 = X + (size_t)((gi0 < count) ? (g_idxl[e * TT + gi0] >> 1) : 0) * DD;
    const float* ar1 = X + (size_t)((gi1 < count) ? (g_idxl[e * TT + gi1] >> 1) : 0) * DD;
    for (int k0 = 0; k0 < DD; k0 += 16) {
        float4 av0 = *(const float4*)(ar0 + k0 + kca0);
        float4 av1 = *(const float4*)(ar1 + k0 + kca1);
        float4 bv0 = *(const float4*)(B + (size_t)(k0 + 2 * bq) * FF + n0 + bnc);
        float4 bv1 = *(const float4*)(B + (size_t)(k0 + 2 * bq + 1) * FF + n0 + bnc);
        store_kpairs(Ahi, Alo, kca0, ma0, av0);
        store_kpairs(Ahi, Alo, kca1, ma1, av1);
        store_npairs(Bhi, Blo, bq, bnc, bv0, bv1);
        __syncthreads();
        bf16_block_mma(cacc, Ahi, Alo, Bhi, Blo, lane, wm, wn);
        __syncthreads();
    }
    int lr = lane >> 2, lc = lane & 3;
    #pragma unroll
    for (int mt = 0; mt < 4; mt++) {
        int r0 = m0 + wm + mt * 16 + lr;
        #pragma unroll
        for (int nt = 0; nt < 4; nt++) {
            int cn = n0 + wn + nt * 8 + lc * 2;
            #pragma unroll
            for (int half = 0; half < 2; half++) {
                int row = r0 + half * 8;
                if (row < count) {
                    size_t cb = ((size_t)e * TT + row) * FF + cn;
                    float ga = cacc[mt][nt][half * 2];
                    float gb = cacc[mt][nt][half * 2 + 1];
                    g_abuf[cb]     = ga / (1.f + expf(-ga)) * g_ubuf[cb];
                    g_abuf[cb + 1] = gb / (1.f + expf(-gb)) * g_ubuf[cb + 1];
                }
            }
        }
    }
}

// ---- MoE down: weighted scatter to g_yslot ----
__global__ void __launch_bounds__(256) tmoe_down_kernel(const float* __restrict__ Wd) {
    int e = blockIdx.z;
    int count = g_counts[e];
    int m0 = blockIdx.y * 128;
    if (m0 >= count) return;
    const float* B = Wd + (size_t)e * FF * DD;
    const int n0 = blockIdx.x * 128;
    TB_PROLOG
    int gi0 = m0 + ma0, gi1 = m0 + ma1;
    const float* ar0 = g_abuf + ((size_t)e * TT + ((gi0 < count) ? gi0 : 0)) * FF;
    const float* ar1 = g_abuf + ((size_t)e * TT + ((gi1 < count) ? gi1 : 0)) * FF;
    for (int k0 = 0; k0 < FF; k0 += 16) {
        float4 av0 = *(const float4*)(ar0 + k0 + kca0);
        float4 av1 = *(const float4*)(ar1 + k0 + kca1);
        float4 bv0 = *(const float4*)(B + (size_t)(k0 + 2 * bq) * DD + n0 + bnc);
        float4 bv1 = *(const float4*)(B + (size_t)(k0 + 2 * bq + 1) * DD + n0 + bnc);
        store_kpairs(Ahi, Alo, kca0, ma0, av0);
        store_kpairs(Ahi, Alo, kca1, ma1, av1);
        store_npairs(Bhi, Blo, bq, bnc, bv0, bv1);
        __syncthreads();
        bf16_block_mma(cacc, Ahi, Alo, Bhi, Blo, lane, wm, wn);
        __syncthreads();
    }
    int lr = lane >> 2, lc = lane & 3;
    #pragma unroll
    for (int mt = 0; mt < 4; mt++) {
        int r0 = m0 + wm + mt * 16 + lr;
        #pragma unroll
        for (int half = 0; half < 2; half++) {
            int row = r0 + half * 8;
            if (row < count) {
                int entry = g_idxl[e * TT + row];
                float wgt = g_wslot[entry];
                #pragma unroll
                for (int nt = 0; nt < 4; nt++) {
                    int cn = n0 + wn + nt * 8 + lc * 2;
                    size_t cb = (size_t)entry * DD + cn;
                    g_yslot[cb]     = cacc[mt][nt][half * 2] * wgt;
                    g_yslot[cb + 1] = cacc[mt][nt][half * 2 + 1] * wgt;
                }
            }
        }
    }
}

// ---------------- routing (verified) ----------------
__global__ void reset_router_kernel() {
    if (threadIdx.x < NE) { g_counts[threadIdx.x] = 0; g_probsum[threadIdx.x] = 0.f; }
}
__global__ void reset_aux_kernel() { g_aux = 0.f; }

__global__ void router_kernel(const float* __restrict__ X, const float* __restrict__ RW) {
    int n = blockIdx.x, tid = threadIdx.x;
    const float* xr = X + (size_t)n * DD;
    float p[NE];
    #pragma unroll
    for (int e = 0; e < NE; e++) p[e] = 0.f;
    for (int d = tid; d < DD; d += 256) {
        float xv = xr[d];
        #pragma unroll
        for (int e = 0; e < NE; e++) p[e] += xv * RW[d * NE + e];
    }
    #pragma unroll
    for (int e = 0; e < NE; e++)
        #pragma unroll
        for (int off = 16; off; off >>= 1) p[e] += __shfl_down_sync(0xffffffffu, p[e], off);
    __shared__ float sred[8][NE];
    int warp = tid >> 5, lane = tid & 31;
    if (lane == 0)
        #pragma unroll
        for (int e = 0; e < NE; e++) sred[warp][e] = p[e];
    __syncthreads();
    if (tid == 0) {
        float lg[NE];
        #pragma unroll
        for (int e = 0; e < NE; e++) {
            float s = 0.f;
            #pragma unroll
            for (int w = 0; w < 8; w++) s += sred[w][e];
            lg[e] = s;
        }
        float mx = lg[0];
        #pragma unroll
        for (int e = 1; e < NE; e++) mx = fmaxf(mx, lg[e]);
        float pb[NE], sum = 0.f;
        #pragma unroll
        for (int e = 0; e < NE; e++) { pb[e] = expf(lg[e] - mx); sum += pb[e]; }
        float isum = 1.f / sum;
        #pragma unroll
        for (int e = 0; e < NE; e++) pb[e] *= isum;
        int e1 = 0;
        #pragma unroll
        for (int e = 1; e < NE; e++) if (pb[e] > pb[e1]) e1 = e;
        int e2 = (e1 == 0) ? 1 : 0;
        #pragma unroll
        for (int e = 0; e < NE; e++) if (e != e1 && pb[e] > pb[e2]) e2 = e;
        float s2 = pb[e1] + pb[e2];
        g_wslot[2 * n]     = pb[e1] / s2;
        g_wslot[2 * n + 1] = pb[e2] / s2;
        int p1 = atomicAdd(&g_counts[e1], 1); g_idxl[e1 * TT + p1] = (n << 1);
        int p2 = atomicAdd(&g_counts[e2], 1); g_idxl[e2 * TT + p2] = (n << 1) | 1;
        #pragma unroll
        for (int e = 0; e < NE; e++) atomicAdd(&g_probsum[e], pb[e]);
    }
}

__global__ void aux_kernel() {
    float s = 0.f;
    #pragma unroll
    for (int e = 0; e < NE; e++) s += g_probsum[e] * (float)g_counts[e];
    g_aux += (float)NE * s / ((float)TT * (float)TT);
}

__global__ void combine_kernel(float* __restrict__ x) {
    int n = blockIdx.x;
    for (int d = threadIdx.x; d < DD; d += 256)
        x[(size_t)n * DD + d] += g_yslot[(size_t)(2 * n) * DD + d] +
                                 g_yslot[(size_t)(2 * n + 1) * DD + d];
}

__global__ void write_aux_kernel(float* __restrict__ out) { out[(size_t)TT * VV] = g_aux; }

// ---------------- launch ----------------
extern "C" void kernel_launch(void* const* d_in, const int* in_sizes, int n_in,
                              void* d_out, int out_size) {
    const int*   tokens = (const int*)d_in[0];
    const float* emb    = (const float*)d_in[1];
    const float* n1w    = (const float*)d_in[2];
    const float* n2w    = (const float*)d_in[3];
    const float* wq     = (const float*)d_in[4];
    const float* wk     = (const float*)d_in[5];
    const float* wv     = (const float*)d_in[6];
    const float* wo     = (const float*)d_in[7];
    const float* rw     = (const float*)d_in[8];
    const float* wg     = (const float*)d_in[9];
    const float* wu     = (const float*)d_in[10];
    const float* wd     = (const float*)d_in[11];
    const float* now    = (const float*)d_in[12];
    float* out = (float*)d_out;

    float *px, *ph, *pq, *pk, *pv, *pa;
    cudaGetSymbolAddress((void**)&px, g_x);
    cudaGetSymbolAddress((void**)&ph, g_h);
    cudaGetSymbolAddress((void**)&pq, g_q);
    cudaGetSymbolAddress((void**)&pk, g_k);
    cudaGetSymbolAddress((void**)&pv, g_v);
    cudaGetSymbolAddress((void**)&pa, g_attn);

    embed_kernel<<<TT * DD / 256, 256>>>(tokens, emb, px);
    rope_table_kernel<<<TT * 32 / 256, 256>>>();
    reset_aux_kernel<<<1, 1>>>();

    for (int l = 0; l < 2; l++) {
        rmsnorm_kernel<<<TT, 256>>>(px, n1w + (size_t)l * DD, ph);
        tgemm_nn_kernel<false><<<dim3((NH * HD) / 128, TT / 128), 256>>>(
            ph, wq + (size_t)l * DD * NH * HD, pq, TT, NH * HD, DD);
        tgemm_nn_kernel<false><<<dim3((NKV * HD) / 128, TT / 128), 256>>>(
            ph, wk + (size_t)l * DD * NKV * HD, pk, TT, NKV * HD, DD);
        tgemm_nn_kernel<false><<<dim3((NKV * HD) / 128, TT / 128), 256>>>(
            ph, wv + (size_t)l * DD * NKV * HD, pv, TT, NKV * HD, DD);
        attn_flash_kernel<<<dim3(TT / 128, NH), 128>>>(pq, pk, pv, pa);
        tgemm_nn_kernel<true><<<dim3(DD / 128, TT / 128), 256>>>(
            pa, wo + (size_t)l * NH * HD * DD, px, TT, DD, NH * HD);

        rmsnorm_kernel<<<TT, 256>>>(px, n2w + (size_t)l * DD, ph);
        reset_router_kernel<<<1, 32>>>();
        router_kernel<<<TT, 256>>>(ph, rw + (size_t)l * DD * NE);
        aux_kernel<<<1, 1>>>();

        tmoe_up_kernel<<<dim3(FF / 128, TT / 128, NE), 256>>>(
            ph, wu + (size_t)l * NE * DD * FF);
        tmoe_gate_kernel<<<dim3(FF / 128, TT / 128, NE), 256>>>(
            ph, wg + (size_t)l * NE * DD * FF);
        tmoe_down_kernel<<<dim3(DD / 128, TT / 128, NE), 256>>>(
            wd + (size_t)l * NE * FF * DD);
        combine_kernel<<<TT, 256>>>(px);
    }

    rmsnorm_kernel<<<TT, 256>>>(px, now, ph);
    tgemm_nt_kernel<<<dim3(VV / 128, TT / 128), 256>>>(ph, emb, out, TT, VV, DD);
    if (out_size > TT * VV) write_aux_kernel<<<1, 1>>>(out);
}

// round 15
// speedup vs baseline: 2.9022x; 1.0084x over previous
#include <cuda_runtime.h>
#include <cuda_bf16.h>
#include <math.h>
#include <stdint.h>

#define TT 2048
#define DD 1024
#define NH 16
#define NKV 4
#define HD 64
#define NE 8
#define FF 2048
#define VV 32000
#define WIN 1024
#define NGLB 32
#define PP 136   // plane pitch (uint32): fragment bank = (8*lc+lr) -> conflict-free

// ---------------- scratch (device globals; allocation-free) ----------------
__device__ float g_x[TT * DD];
__device__ float g_h[TT * DD];
__device__ float g_q[TT * NH * HD];
__device__ float g_k[TT * NKV * HD];
__device__ float g_v[TT * NKV * HD];
__device__ float g_attn[TT * DD];
__device__ float g_cos[TT * 32];
__device__ float g_sin[TT * 32];
__device__ float g_ubuf[NE * TT * FF];
__device__ float g_abuf[NE * TT * FF];
__device__ float g_yslot[TT * 2 * DD];
__device__ float g_wslot[TT * 2];
__device__ int   g_idxl[NE * TT];
__device__ int   g_counts[NE];
__device__ float g_probsum[NE];
__device__ float g_aux;

// ---------------- small kernels ----------------
__global__ void embed_kernel(const int* __restrict__ tok, const float* __restrict__ emb,
                             float* __restrict__ x) {
    int idx = blockIdx.x * 256 + threadIdx.x;
    int t = idx >> 10, d = idx & 1023;
    x[idx] = emb[(size_t)tok[t] * DD + d];
}

__global__ void rope_table_kernel() {
    int idx = blockIdx.x * 256 + threadIdx.x;
    int t = idx >> 5, i = idx & 31;
    float inv = 1.0f / powf(500000.0f, (float)(2 * i) * (1.0f / 64.0f));
    float ang = (float)t * inv;
    g_cos[idx] = cosf(ang);
    g_sin[idx] = sinf(ang);
}

__global__ void rmsnorm_kernel(const float* __restrict__ x, const float* __restrict__ w,
                               float* __restrict__ o) {
    int t = blockIdx.x, tid = threadIdx.x;
    const float* xr = x + (size_t)t * DD;
    float ss = 0.f;
    for (int d = tid; d < DD; d += 256) { float v = xr[d]; ss += v * v; }
    #pragma unroll
    for (int off = 16; off; off >>= 1) ss += __shfl_down_sync(0xffffffffu, ss, off);
    __shared__ float sred[8];
    __shared__ float sinv;
    if ((tid & 31) == 0) sred[tid >> 5] = ss;
    __syncthreads();
    if (tid == 0) {
        float tot = 0.f;
        #pragma unroll
        for (int i = 0; i < 8; i++) tot += sred[i];
        sinv = rsqrtf(tot * (1.0f / DD) + 1.1920929e-07f);
    }
    __syncthreads();
    float inv = sinv;
    for (int d = tid; d < DD; d += 256) o[(size_t)t * DD + d] = xr[d] * inv * w[d];
}

// ---------------- flash attention (verified R10; __expf) ----------------
__global__ void __launch_bounds__(128) attn_flash_kernel(const float* __restrict__ q,
                                                         const float* __restrict__ k,
                                                         const float* __restrict__ v,
                                                         float* __restrict__ out) {
    int h = blockIdx.y;
    int qs = blockIdx.x * 128;
    int i = qs + threadIdx.x;
    int kvh = h >> 2;
    __shared__ float Ksh[32][64];
    __shared__ float Vsh[32][64];
    float qr[64];
    {
        const float* qrow = q + (size_t)i * (NH * HD) + h * HD;
        const float* ci = g_cos + i * 32;
        const float* si = g_sin + i * 32;
        #pragma unroll
        for (int d = 0; d < 32; d++) {
            float c = ci[d], s = si[d];
            float a = qrow[d], b = qrow[d + 32];
            qr[d]      = (a * c - b * s) * 0.125f;
            qr[d + 32] = (b * c + a * s) * 0.125f;
        }
    }
    float m = -1e30f, l = 0.f;
    float acc[64];
    #pragma unroll
    for (int d = 0; d < 64; d++) acc[d] = 0.f;

    for (int j0 = 0; j0 <= qs + 127; j0 += 32) {
        if (j0 >= NGLB && j0 + 31 < qs - WIN + 1) continue;
        for (int e = threadIdx.x; e < 32 * 64; e += 128) {
            int jj = e >> 6, d = e & 63;
            int j = j0 + jj;
            const float* kr = k + (size_t)j * (NKV * HD) + kvh * HD;
            float val;
            if (d < 32) {
                float c = g_cos[j * 32 + d], s = g_sin[j * 32 + d];
                val = kr[d] * c - kr[d + 32] * s;
            } else {
                int d2 = d - 32;
                float c = g_cos[j * 32 + d2], s = g_sin[j * 32 + d2];
                val = kr[d] * c + kr[d2] * s;
            }
            Ksh[jj][d] = val;
            Vsh[jj][d] = v[(size_t)j * (NKV * HD) + kvh * HD + d];
        }
        __syncthreads();
        float s[32];
        #pragma unroll
        for (int jj = 0; jj < 32; jj++) {
            float a = 0.f;
            #pragma unroll
            for (int d = 0; d < 64; d++) a += qr[d] * Ksh[jj][d];
            int j = j0 + jj;
            bool ok = (j <= i) && ((i - j) < WIN || j < NGLB);
            s[jj] = ok ? a : -1e30f;
        }
        float mt = -1e30f;
        #pragma unroll
        for (int jj = 0; jj < 32; jj++) mt = fmaxf(mt, s[jj]);
        if (mt > -1e29f) {
            float mn = fmaxf(m, mt);
            float f = __expf(m - mn);
            l *= f;
            #pragma unroll
            for (int d = 0; d < 64; d++) acc[d] *= f;
            #pragma unroll
            for (int jj = 0; jj < 32; jj++) {
                float pj = __expf(s[jj] - mn);
                l += pj;
                #pragma unroll
                for (int d = 0; d < 64; d++) acc[d] += pj * Vsh[jj][d];
            }
            m = mn;
        }
        __syncthreads();
    }
    float il = 1.0f / l;
    #pragma unroll
    for (int d = 0; d < 64; d++) out[(size_t)i * (NH * HD) + h * HD + d] = acc[d] * il;
}

// ---------------- bf16x3 tensor-core GEMM core (BK=32) ----------------
__device__ __forceinline__ void split2(float x0, float x1, uint32_t& hi, uint32_t& lo) {
    __nv_bfloat162 h = __floats2bfloat162_rn(x0, x1);
    float h0 = __bfloat162float(h.x), h1 = __bfloat162float(h.y);
    __nv_bfloat162 l = __floats2bfloat162_rn(x0 - h0, x1 - h1);
    hi = *reinterpret_cast<uint32_t*>(&h);
    lo = *reinterpret_cast<uint32_t*>(&l);
}

__device__ __forceinline__ void store_kpairs(uint32_t* Phi, uint32_t* Plo,
                                             int kc, int col, float4 v) {
    uint32_t h0, l0, h1, l1;
    split2(v.x, v.y, h0, l0);
    split2(v.z, v.w, h1, l1);
    int q = kc >> 1;
    Phi[q * PP + col] = h0;       Plo[q * PP + col] = l0;
    Phi[(q + 1) * PP + col] = h1; Plo[(q + 1) * PP + col] = l1;
}

__device__ __forceinline__ void store_npairs(uint32_t* Phi, uint32_t* Plo,
                                             int q, int nc, float4 v0, float4 v1) {
    uint32_t h, l;
    split2(v0.x, v1.x, h, l); Phi[q * PP + nc] = h;     Plo[q * PP + nc] = l;
    split2(v0.y, v1.y, h, l); Phi[q * PP + nc + 1] = h; Plo[q * PP + nc + 1] = l;
    split2(v0.z, v1.z, h, l); Phi[q * PP + nc + 2] = h; Plo[q * PP + nc + 2] = l;
    split2(v0.w, v1.w, h, l); Phi[q * PP + nc + 3] = h; Plo[q * PP + nc + 3] = l;
}

__device__ __forceinline__ void mma16(float* c, uint32_t a0, uint32_t a1, uint32_t a2,
                                      uint32_t a3, uint32_t b0, uint32_t b1) {
    asm volatile(
        "mma.sync.aligned.m16n8k16.row.col.f32.bf16.bf16.f32 "
        "{%0,%1,%2,%3}, {%4,%5,%6,%7}, {%8,%9}, {%0,%1,%2,%3};"
        : "+f"(c[0]), "+f"(c[1]), "+f"(c[2]), "+f"(c[3])
        : "r"(a0), "r"(a1), "r"(a2), "r"(a3), "r"(b0), "r"(b1));
}

// planes hold 16 k-pair rows (BK=32); mma over two k16 sub-steps.
__device__ __forceinline__ void bf16_block_mma(float (*cacc)[4][4],
                                               const uint32_t* Ahi, const uint32_t* Alo,
                                               const uint32_t* Bhi, const uint32_t* Blo,
                                               int lane, int wm, int wn) {
    int lr = lane >> 2, lc = lane & 3;
    #pragma unroll
    for (int kq = 0; kq < 16; kq += 8) {
        uint32_t bh0[4], bh1[4], bl0[4], bl1[4];
        #pragma unroll
        for (int nt = 0; nt < 4; nt++) {
            int n = wn + nt * 8 + lr;
            bh0[nt] = Bhi[(kq + lc) * PP + n];     bh1[nt] = Bhi[(kq + lc + 4) * PP + n];
            bl0[nt] = Blo[(kq + lc) * PP + n];     bl1[nt] = Blo[(kq + lc + 4) * PP + n];
        }
        #pragma unroll
        for (int mt = 0; mt < 4; mt++) {
            int m = wm + mt * 16 + lr;
            uint32_t ah0 = Ahi[(kq + lc) * PP + m],     ah1 = Ahi[(kq + lc) * PP + m + 8];
            uint32_t ah2 = Ahi[(kq + lc + 4) * PP + m], ah3 = Ahi[(kq + lc + 4) * PP + m + 8];
            uint32_t al0 = Alo[(kq + lc) * PP + m],     al1 = Alo[(kq + lc) * PP + m + 8];
            uint32_t al2 = Alo[(kq + lc + 4) * PP + m], al3 = Alo[(kq + lc + 4) * PP + m + 8];
            #pragma unroll
            for (int nt = 0; nt < 4; nt++) {
                mma16(cacc[mt][nt], ah0, ah1, ah2, ah3, bh0[nt], bh1[nt]);
                mma16(cacc[mt][nt], al0, al1, al2, al3, bh0[nt], bh1[nt]);
                mma16(cacc[mt][nt], ah0, ah1, ah2, ah3, bl0[nt], bl1[nt]);
            }
        }
    }
}

#define TB_PROLOG                                                              \
    __shared__ uint32_t Ahi[16 * PP], Alo[16 * PP], Bhi[16 * PP], Blo[16 * PP];\
    const int tid = threadIdx.x, lane = tid & 31, warp = tid >> 5;             \
    const int wm = (warp >> 2) * 64, wn = (warp & 3) * 32;                     \
    const int t2 = tid * 2;                                                    \
    const int ma0 = t2 >> 2, kca0 = (t2 & 3) * 4;                              \
    const int ma1 = (t2 + 1) >> 2, kca1 = ((t2 + 1) & 3) * 4;                  \
    const int bq = tid >> 5, bnc = (tid & 31) * 4;                             \
    float cacc[4][4][4];                                                       \
    _Pragma("unroll") for (int i = 0; i < 4; i++)                              \
        _Pragma("unroll") for (int j = 0; j < 4; j++)                          \
            _Pragma("unroll") for (int r = 0; r < 4; r++) cacc[i][j][r] = 0.f;

// ---- generic NN (B row-major [K][N]) with optional C += ----
template <bool ADD>
__global__ void __launch_bounds__(256) tgemm_nn_kernel(const float* __restrict__ A,
                                                       const float* __restrict__ B,
                                                       float* __restrict__ C,
                                                       int M, int N, int K) {
    const int m0 = blockIdx.y * 128, n0 = blockIdx.x * 128;
    TB_PROLOG
    for (int k0 = 0; k0 < K; k0 += 32) {
        #pragma unroll
        for (int kh = 0; kh < 32; kh += 16) {
            float4 av0 = *(const float4*)(A + (size_t)(m0 + ma0) * K + k0 + kh + kca0);
            float4 av1 = *(const float4*)(A + (size_t)(m0 + ma1) * K + k0 + kh + kca1);
            float4 bv0 = *(const float4*)(B + (size_t)(k0 + kh + 2 * bq) * N + n0 + bnc);
            float4 bv1 = *(const float4*)(B + (size_t)(k0 + kh + 2 * bq + 1) * N + n0 + bnc);
            store_kpairs(Ahi, Alo, kh + kca0, ma0, av0);
            store_kpairs(Ahi, Alo, kh + kca1, ma1, av1);
            store_npairs(Bhi, Blo, (kh >> 1) + bq, bnc, bv0, bv1);
        }
        __syncthreads();
        bf16_block_mma(cacc, Ahi, Alo, Bhi, Blo, lane, wm, wn);
        __syncthreads();
    }
    int lr = lane >> 2, lc = lane & 3;
    #pragma unroll
    for (int mt = 0; mt < 4; mt++) {
        int r0 = m0 + wm + mt * 16 + lr;
        #pragma unroll
        for (int nt = 0; nt < 4; nt++) {
            size_t c0 = (size_t)r0 * N + n0 + wn + nt * 8 + lc * 2;
            size_t c1 = (size_t)(r0 + 8) * N + n0 + wn + nt * 8 + lc * 2;
            if (ADD) {
                C[c0] += cacc[mt][nt][0]; C[c0 + 1] += cacc[mt][nt][1];
                C[c1] += cacc[mt][nt][2]; C[c1 + 1] += cacc[mt][nt][3];
            } else {
                C[c0] = cacc[mt][nt][0]; C[c0 + 1] = cacc[mt][nt][1];
                C[c1] = cacc[mt][nt][2]; C[c1 + 1] = cacc[mt][nt][3];
            }
        }
    }
}

// ---- NT (B row-major [N][K]; lm_head) ----
__global__ void __launch_bounds__(256) tgemm_nt_kernel(const float* __restrict__ A,
                                                       const float* __restrict__ B,
                                                       float* __restrict__ C,
                                                       int M, int N, int K) {
    const int m0 = blockIdx.y * 128, n0 = blockIdx.x * 128;
    TB_PROLOG
    for (int k0 = 0; k0 < K; k0 += 32) {
        #pragma unroll
        for (int kh = 0; kh < 32; kh += 16) {
            float4 av0 = *(const float4*)(A + (size_t)(m0 + ma0) * K + k0 + kh + kca0);
            float4 av1 = *(const float4*)(A + (size_t)(m0 + ma1) * K + k0 + kh + kca1);
            float4 bv0 = *(const float4*)(B + (size_t)(n0 + ma0) * K + k0 + kh + kca0);
            float4 bv1 = *(const float4*)(B + (size_t)(n0 + ma1) * K + k0 + kh + kca1);
            store_kpairs(Ahi, Alo, kh + kca0, ma0, av0);
            store_kpairs(Ahi, Alo, kh + kca1, ma1, av1);
            store_kpairs(Bhi, Blo, kh + kca0, ma0, bv0);
            store_kpairs(Bhi, Blo, kh + kca1, ma1, bv1);
        }
        __syncthreads();
        bf16_block_mma(cacc, Ahi, Alo, Bhi, Blo, lane, wm, wn);
        __syncthreads();
    }
    int lr = lane >> 2, lc = lane & 3;
    #pragma unroll
    for (int mt = 0; mt < 4; mt++) {
        int r0 = m0 + wm + mt * 16 + lr;
        #pragma unroll
        for (int nt = 0; nt < 4; nt++) {
            size_t c0 = (size_t)r0 * N + n0 + wn + nt * 8 + lc * 2;
            size_t c1 = (size_t)(r0 + 8) * N + n0 + wn + nt * 8 + lc * 2;
            C[c0] = cacc[mt][nt][0]; C[c0 + 1] = cacc[mt][nt][1];
            C[c1] = cacc[mt][nt][2]; C[c1 + 1] = cacc[mt][nt][3];
        }
    }
}

// ---- MoE up ----
__global__ void __launch_bounds__(256) tmoe_up_kernel(const float* __restrict__ X,
                                                      const float* __restrict__ Wu) {
    int e = blockIdx.z;
    int count = g_counts[e];
    int m0 = blockIdx.y * 128;
    if (m0 >= count) return;
    const float* B = Wu + (size_t)e * DD * FF;
    const int n0 = blockIdx.x * 128;
    TB_PROLOG
    int gi0 = m0 + ma0, gi1 = m0 + ma1;
    const float* ar0 = X + (size_t)((gi0 < count) ? (g_idxl[e * TT + gi0] >> 1) : 0) * DD;
    const float* ar1 = X + (size_t)((gi1 < count) ? (g_idxl[e * TT + gi1] >> 1) : 0) * DD;
    for (int k0 = 0; k0 < DD; k0 += 32) {
        #pragma unroll
        for (int kh = 0; kh < 32; kh += 16) {
            float4 av0 = *(const float4*)(ar0 + k0 + kh + kca0);
            float4 av1 = *(const float4*)(ar1 + k0 + kh + kca1);
            float4 bv0 = *(const float4*)(B + (size_t)(k0 + kh + 2 * bq) * FF + n0 + bnc);
            float4 bv1 = *(const float4*)(B + (size_t)(k0 + kh + 2 * bq + 1) * FF + n0 + bnc);
            store_kpairs(Ahi, Alo, kh + kca0, ma0, av0);
            store_kpairs(Ahi, Alo, kh + kca1, ma1, av1);
            store_npairs(Bhi, Blo, (kh >> 1) + bq, bnc, bv0, bv1);
        }
        __syncthreads();
        bf16_block_mma(cacc, Ahi, Alo, Bhi, Blo, lane, wm, wn);
        __syncthreads();
    }
    int lr = lane >> 2, lc = lane & 3;
    #pragma unroll
    for (int mt = 0; mt < 4; mt++) {
        int r0 = m0 + wm + mt * 16 + lr;
        #pragma unroll
        for (int nt = 0; nt < 4; nt++) {
            int cn = n0 + wn + nt * 8 + lc * 2;
            if (r0 < count) {
                size_t cb = ((size_t)e * TT + r0) * FF + cn;
                g_ubuf[cb] = cacc[mt][nt][0]; g_ubuf[cb + 1] = cacc[mt][nt][1];
            }
            if (r0 + 8 < count) {
                size_t cb = ((size_t)e * TT + r0 + 8) * FF + cn;
                g_ubuf[cb] = cacc[mt][nt][2]; g_ubuf[cb + 1] = cacc[mt][nt][3];
            }
        }
    }
}

// ---- MoE gate: epilogue silu(g)*ubuf -> g_abuf ----
__global__ void __launch_bounds__(256) tmoe_gate_kernel(const float* __restrict__ X,
                                                        const float* __restrict__ Wg) {
    int e = blockIdx.z;
    int count = g_counts[e];
    int m0 = blockIdx.y * 128;
    if (m0 >= count) return;
    const float* B = Wg + (size_t)e * DD * FF;
    const int n0 = blockIdx.x * 128;
    TB_PROLOG
    int gi0 = m0 + ma0, gi1 = m0 + ma1;
    const float* ar0 = X + (size_t)((gi0 < count) ? (g_idxl[e * TT + gi0] >> 1) : 0) * DD;
    const float* ar1 = X + (size_t)((gi1 < count) ? (g_idxl[e * TT + gi1] >> 1) : 0) * DD;
    for (int k0 = 0; k0 < DD; k0 += 32) {
        #pragma unroll
        for (int kh = 0; kh < 32; kh += 16) {
            float4 av0 = *(const float4*)(ar0 + k0 + kh + kca0);
            float4 av1 = *(const float4*)(ar1 + k0 + kh + kca1);
            float4 bv0 = *(const float4*)(B + (size_t)(k0 + kh + 2 * bq) * FF + n0 + bnc);
            float4 bv1 = *(const float4*)(B + (size_t)(k0 + kh + 2 * bq + 1) * FF + n0 + bnc);
            store_kpairs(Ahi, Alo, kh + kca0, ma0, av0);
            store_kpairs(Ahi, Alo, kh + kca1, ma1, av1);
            store_npairs(Bhi, Blo, (kh >> 1) + bq, bnc, bv0, bv1);
        }
        __syncthreads();
        bf16_block_mma(cacc, Ahi, Alo, Bhi, Blo, lane, wm, wn);
        __syncthreads();
    }
    int lr = lane >> 2, lc = lane & 3;
    #pragma unroll
    for (int mt = 0; mt < 4; mt++) {
        int r0 = m0 + wm + mt * 16 + lr;
        #pragma unroll
        for (int nt = 0; nt < 4; nt++) {
            int cn = n0 + wn + nt * 8 + lc * 2;
            #pragma unroll
            for (int half = 0; half < 2; half++) {
                int row = r0 + half * 8;
                if (row < count) {
                    size_t cb = ((size_t)e * TT + row) * FF + cn;
                    float ga = cacc[mt][nt][half * 2];
                    float gb = cacc[mt][nt][half * 2 + 1];
                    g_abuf[cb]     = ga / (1.f + __expf(-ga)) * g_ubuf[cb];
                    g_abuf[cb + 1] = gb / (1.f + __expf(-gb)) * g_ubuf[cb + 1];
                }
            }
        }
    }
}

// ---- MoE down: weighted scatter to g_yslot ----
__global__ void __launch_bounds__(256) tmoe_down_kernel(const float* __restrict__ Wd) {
    int e = blockIdx.z;
    int count = g_counts[e];
    int m0 = blockIdx.y * 128;
    if (m0 >= count) return;
    const float* B = Wd + (size_t)e * FF * DD;
    const int n0 = blockIdx.x * 128;
    TB_PROLOG
    int gi0 = m0 + ma0, gi1 = m0 + ma1;
    const float* ar0 = g_abuf + ((size_t)e * TT + ((gi0 < count) ? gi0 : 0)) * FF;
    const float* ar1 = g_abuf + ((size_t)e * TT + ((gi1 < count) ? gi1 : 0)) * FF;
    for (int k0 = 0; k0 < FF; k0 += 32) {
        #pragma unroll
        for (int kh = 0; kh < 32; kh += 16) {
            float4 av0 = *(const float4*)(ar0 + k0 + kh + kca0);
            float4 av1 = *(const float4*)(ar1 + k0 + kh + kca1);
            float4 bv0 = *(const float4*)(B + (size_t)(k0 + kh + 2 * bq) * DD + n0 + bnc);
            float4 bv1 = *(const float4*)(B + (size_t)(k0 + kh + 2 * bq + 1) * DD + n0 + bnc);
            store_kpairs(Ahi, Alo, kh + kca0, ma0, av0);
            store_kpairs(Ahi, Alo, kh + kca1, ma1, av1);
            store_npairs(Bhi, Blo, (kh >> 1) + bq, bnc, bv0, bv1);
        }
        __syncthreads();
        bf16_block_mma(cacc, Ahi, Alo, Bhi, Blo, lane, wm, wn);
        __syncthreads();
    }
    int lr = lane >> 2, lc = lane & 3;
    #pragma unroll
    for (int mt = 0; mt < 4; mt++) {
        int r0 = m0 + wm + mt * 16 + lr;
        #pragma unroll
        for (int half = 0; half < 2; half++) {
            int row = r0 + half * 8;
            if (row < count) {
                int entry = g_idxl[e * TT + row];
                float wgt = g_wslot[entry];
                #pragma unroll
                for (int nt = 0; nt < 4; nt++) {
                    int cn = n0 + wn + nt * 8 + lc * 2;
                    size_t cb = (size_t)entry * DD + cn;
                    g_yslot[cb]     = cacc[mt][nt][half * 2] * wgt;
                    g_yslot[cb + 1] = cacc[mt][nt][half * 2 + 1] * wgt;
                }
            }
        }
    }
}

// ---------------- routing (verified) ----------------
__global__ void reset_router_kernel() {
    if (threadIdx.x < NE) { g_counts[threadIdx.x] = 0; g_probsum[threadIdx.x] = 0.f; }
}
__global__ void reset_aux_kernel() { g_aux = 0.f; }

__global__ void router_kernel(const float* __restrict__ X, const float* __restrict__ RW) {
    int n = blockIdx.x, tid = threadIdx.x;
    const float* xr = X + (size_t)n * DD;
    float p[NE];
    #pragma unroll
    for (int e = 0; e < NE; e++) p[e] = 0.f;
    for (int d = tid; d < DD; d += 256) {
        float xv = xr[d];
        #pragma unroll
        for (int e = 0; e < NE; e++) p[e] += xv * RW[d * NE + e];
    }
    #pragma unroll
    for (int e = 0; e < NE; e++)
        #pragma unroll
        for (int off = 16; off; off >>= 1) p[e] += __shfl_down_sync(0xffffffffu, p[e], off);
    __shared__ float sred[8][NE];
    int warp = tid >> 5, lane = tid & 31;
    if (lane == 0)
        #pragma unroll
        for (int e = 0; e < NE; e++) sred[warp][e] = p[e];
    __syncthreads();
    if (tid == 0) {
        float lg[NE];
        #pragma unroll
        for (int e = 0; e < NE; e++) {
            float s = 0.f;
            #pragma unroll
            for (int w = 0; w < 8; w++) s += sred[w][e];
            lg[e] = s;
        }
        float mx = lg[0];
        #pragma unroll
        for (int e = 1; e < NE; e++) mx = fmaxf(mx, lg[e]);
        float pb[NE], sum = 0.f;
        #pragma unroll
        for (int e = 0; e < NE; e++) { pb[e] = expf(lg[e] - mx); sum += pb[e]; }
        float isum = 1.f / sum;
        #pragma unroll
        for (int e = 0; e < NE; e++) pb[e] *= isum;
        int e1 = 0;
        #pragma unroll
        for (int e = 1; e < NE; e++) if (pb[e] > pb[e1]) e1 = e;
        int e2 = (e1 == 0) ? 1 : 0;
        #pragma unroll
        for (int e = 0; e < NE; e++) if (e != e1 && pb[e] > pb[e2]) e2 = e;
        float s2 = pb[e1] + pb[e2];
        g_wslot[2 * n]     = pb[e1] / s2;
        g_wslot[2 * n + 1] = pb[e2] / s2;
        int p1 = atomicAdd(&g_counts[e1], 1); g_idxl[e1 * TT + p1] = (n << 1);
        int p2 = atomicAdd(&g_counts[e2], 1); g_idxl[e2 * TT + p2] = (n << 1) | 1;
        #pragma unroll
        for (int e = 0; e < NE; e++) atomicAdd(&g_probsum[e], pb[e]);
    }
}

__global__ void aux_kernel() {
    float s = 0.f;
    #pragma unroll
    for (int e = 0; e < NE; e++) s += g_probsum[e] * (float)g_counts[e];
    g_aux += (float)NE * s / ((float)TT * (float)TT);
}

__global__ void combine_kernel(float* __restrict__ x) {
    int n = blockIdx.x;
    for (int d = threadIdx.x; d < DD; d += 256)
        x[(size_t)n * DD + d] += g_yslot[(size_t)(2 * n) * DD + d] +
                                 g_yslot[(size_t)(2 * n + 1) * DD + d];
}

__global__ void write_aux_kernel(float* __restrict__ out) { out[(size_t)TT * VV] = g_aux; }

// ---------------- launch ----------------
extern "C" void kernel_launch(void* const* d_in, const int* in_sizes, int n_in,
                              void* d_out, int out_size) {
    const int*   tokens = (const int*)d_in[0];
    const float* emb    = (const float*)d_in[1];
    const float* n1w    = (const float*)d_in[2];
    const float* n2w    = (const float*)d_in[3];
    const float* wq     = (const float*)d_in[4];
    const float* wk     = (const float*)d_in[5];
    const float* wv     = (const float*)d_in[6];
    const float* wo     = (const float*)d_in[7];
    const float* rw     = (const float*)d_in[8];
    const float* wg     = (const float*)d_in[9];
    const float* wu     = (const float*)d_in[10];
    const float* wd     = (const float*)d_in[11];
    const float* now    = (const float*)d_in[12];
    float* out = (float*)d_out;

    float *px, *ph, *pq, *pk, *pv, *pa;
    cudaGetSymbolAddress((void**)&px, g_x);
    cudaGetSymbolAddress((void**)&ph, g_h);
    cudaGetSymbolAddress((void**)&pq, g_q);
    cudaGetSymbolAddress((void**)&pk, g_k);
    cudaGetSymbolAddress((void**)&pv, g_v);
    cudaGetSymbolAddress((void**)&pa, g_attn);

    embed_kernel<<<TT * DD / 256, 256>>>(tokens, emb, px);
    rope_table_kernel<<<TT * 32 / 256, 256>>>();
    reset_aux_kernel<<<1, 1>>>();

    for (int l = 0; l < 2; l++) {
        rmsnorm_kernel<<<TT, 256>>>(px, n1w + (size_t)l * DD, ph);
        tgemm_nn_kernel<false><<<dim3((NH * HD) / 128, TT / 128), 256>>>(
            ph, wq + (size_t)l * DD * NH * HD, pq, TT, NH * HD, DD);
        tgemm_nn_kernel<false><<<dim3((NKV * HD) / 128, TT / 128), 256>>>(
            ph, wk + (size_t)l * DD * NKV * HD, pk, TT, NKV * HD, DD);
        tgemm_nn_kernel<false><<<dim3((NKV * HD) / 128, TT / 128), 256>>>(
            ph, wv + (size_t)l * DD * NKV * HD, pv, TT, NKV * HD, DD);
        attn_flash_kernel<<<dim3(TT / 128, NH), 128>>>(pq, pk, pv, pa);
        tgemm_nn_kernel<true><<<dim3(DD / 128, TT / 128), 256>>>(
            pa, wo + (size_t)l * NH * HD * DD, px, TT, DD, NH * HD);

        rmsnorm_kernel<<<TT, 256>>>(px, n2w + (size_t)l * DD, ph);
        reset_router_kernel<<<1, 32>>>();
        router_kernel<<<TT, 256>>>(ph, rw + (size_t)l * DD * NE);
        aux_kernel<<<1, 1>>>();

        tmoe_up_kernel<<<dim3(FF / 128, TT / 128, NE), 256>>>(
            ph, wu + (size_t)l * NE * DD * FF);
        tmoe_gate_kernel<<<dim3(FF / 128, TT / 128, NE), 256>>>(
            ph, wg + (size_t)l * NE * DD * FF);
        tmoe_down_kernel<<<dim3(DD / 128, TT / 128, NE), 256>>>(
            wd + (size_t)l * NE * FF * DD);
        combine_kernel<<<TT, 256>>>(px);
    }

    rmsnorm_kernel<<<TT, 256>>>(px, now, ph);
    tgemm_nt_kernel<<<dim3(VV / 128, TT / 128), 256>>>(ph, emb, out, TT, VV, DD);
    if (out_size > TT * VV) write_aux_kernel<<<1, 1>>>(out);
}